// round 2
// baseline (speedup 1.0000x reference)
#include <cuda_runtime.h>
#include <cuda_bf16.h>
#include <math.h>

// Problem constants (fixed shapes in the dataset)
#define D_MODEL   512
#define D_FIBER   32
#define D_CONTROL 64
#define SEQ_S     4096

// GEMM tiling
#define TM 128          // tokens per block
#define TN 96           // 32 fiber + 64 h-pre columns
#define TK 16           // k-chunk
#define NKT (D_MODEL / TK)   // 32
#define THREADS 256
#define AS_STRIDE 132   // padded TM stride (multiple of 4, breaks bank conflicts)

struct SmemA {
    float As[2][TK][AS_STRIDE];   // A chunk, [k][m] layout (m contiguous)
    float Bs[2][TK][TN];          // B chunk, [k][n]
    float Fs[TM][33];             // fiber tile (padded)
    float Ws2[32][64];            // w1 rows 512..543 (fiber part)
    float Hs[TM][65];             // gelu(h) tile (padded)
    float b1s[64];
    float w2s[64];
    float bfs[32];
};

__global__ __launch_bounds__(THREADS, 2)
void cf_gemm_kernel(const float* __restrict__ hidden,
                    const float* __restrict__ wf,
                    const float* __restrict__ bf,
                    const float* __restrict__ w1,
                    const float* __restrict__ b1,
                    const float* __restrict__ w2,
                    const float* __restrict__ b2,
                    float* __restrict__ fiber_out,
                    float* __restrict__ delta_out)
{
    extern __shared__ char smem_raw[];
    SmemA* s = reinterpret_cast<SmemA*>(smem_raw);

    const int tid = threadIdx.x;
    const int mblock = blockIdx.x * TM;

    // thread tile mapping: 16 n-groups x 16 m-groups, each thread 8m x 6n
    const int nt = tid & 15;
    const int mt = tid >> 4;
    const int n0 = nt * 6;
    const int m0 = mt * 8;

    // --- preload small constants / fiber-part weights ---
    if (tid < 64) {
        s->b1s[tid] = b1[tid];
        s->w2s[tid] = w2[tid];
    }
    if (tid < 32) s->bfs[tid] = bf[tid];
    for (int i = tid; i < 32 * 64; i += THREADS)
        s->Ws2[i >> 6][i & 63] = w1[(D_MODEL + (i >> 6)) * D_CONTROL + (i & 63)];

    // --- per-thread load indices (constant across k-chunks) ---
    // A: 128 rows * 16 k = 512 float4; 2 per thread
    const int arow0 = tid >> 2;          // 0..63
    const int ac    = tid & 3;           // float4 column within chunk
    const int arow1 = arow0 + 64;
    const float* aptr0 = hidden + (size_t)(mblock + arow0) * D_MODEL + ac * 4;
    const float* aptr1 = hidden + (size_t)(mblock + arow1) * D_MODEL + ac * 4;
    // B: 16*96 = 1536 floats; 6 per thread
    int kB[6], nB[6];
#pragma unroll
    for (int j = 0; j < 6; ++j) {
        int i = tid + j * THREADS;
        kB[j] = i / TN;
        nB[j] = i - kB[j] * TN;
    }

    // --- initial chunk load (k0 = 0) into buffer 0 ---
    {
        float4 v0 = *(const float4*)(aptr0);
        float4 v1 = *(const float4*)(aptr1);
        int kk = ac * 4;
        s->As[0][kk + 0][arow0] = v0.x; s->As[0][kk + 1][arow0] = v0.y;
        s->As[0][kk + 2][arow0] = v0.z; s->As[0][kk + 3][arow0] = v0.w;
        s->As[0][kk + 0][arow1] = v1.x; s->As[0][kk + 1][arow1] = v1.y;
        s->As[0][kk + 2][arow1] = v1.z; s->As[0][kk + 3][arow1] = v1.w;
#pragma unroll
        for (int j = 0; j < 6; ++j) {
            int k = kB[j], n = nB[j];
            float v = (n < D_FIBER) ? wf[k * D_FIBER + n]
                                    : w1[k * D_CONTROL + (n - D_FIBER)];
            s->Bs[0][k][n] = v;
        }
    }
    __syncthreads();

    float acc[8][6];
#pragma unroll
    for (int i = 0; i < 8; ++i)
#pragma unroll
        for (int j = 0; j < 6; ++j) acc[i][j] = 0.0f;

    // --- main K loop, double buffered ---
    for (int kt = 0; kt < NKT; ++kt) {
        const int cur = kt & 1;
        float4 av0, av1;
        float bv[6];
        const bool pref = (kt + 1) < NKT;
        if (pref) {
            const int k0n = (kt + 1) * TK;
            av0 = *(const float4*)(aptr0 + k0n);
            av1 = *(const float4*)(aptr1 + k0n);
#pragma unroll
            for (int j = 0; j < 6; ++j) {
                int k = kB[j], n = nB[j];
                bv[j] = (n < D_FIBER) ? wf[(k0n + k) * D_FIBER + n]
                                      : w1[(k0n + k) * D_CONTROL + (n - D_FIBER)];
            }
        }

        // compute on current buffer
#pragma unroll
        for (int k = 0; k < TK; ++k) {
            const float4* ap = (const float4*)&s->As[cur][k][m0];
            float4 a0 = ap[0];
            float4 a1 = ap[1];
            float a[8] = {a0.x, a0.y, a0.z, a0.w, a1.x, a1.y, a1.z, a1.w};
            float b[6];
#pragma unroll
            for (int j = 0; j < 6; ++j) b[j] = s->Bs[cur][k][n0 + j];
#pragma unroll
            for (int i = 0; i < 8; ++i)
#pragma unroll
                for (int j = 0; j < 6; ++j)
                    acc[i][j] = fmaf(a[i], b[j], acc[i][j]);
        }

        if (pref) {
            const int nxt = cur ^ 1;
            int kk = ac * 4;
            s->As[nxt][kk + 0][arow0] = av0.x; s->As[nxt][kk + 1][arow0] = av0.y;
            s->As[nxt][kk + 2][arow0] = av0.z; s->As[nxt][kk + 3][arow0] = av0.w;
            s->As[nxt][kk + 0][arow1] = av1.x; s->As[nxt][kk + 1][arow1] = av1.y;
            s->As[nxt][kk + 2][arow1] = av1.z; s->As[nxt][kk + 3][arow1] = av1.w;
#pragma unroll
            for (int j = 0; j < 6; ++j) s->Bs[nxt][kB[j]][nB[j]] = bv[j];
        }
        __syncthreads();
    }

    // --- fiber epilogue: write fiber output + stash in smem ---
#pragma unroll
    for (int j = 0; j < 6; ++j) {
        const int n = n0 + j;
        if (n < D_FIBER) {
#pragma unroll
            for (int i = 0; i < 8; ++i) {
                float v = acc[i][j] + s->bfs[n];
                s->Fs[m0 + i][n] = v;
                fiber_out[(size_t)(mblock + m0 + i) * D_FIBER + n] = v;
            }
        }
    }
    __syncthreads();

    // --- h columns: add fiber @ w1[512:544], bias, exact GELU ---
    if (n0 + 5 >= D_FIBER) {
        for (int kf = 0; kf < D_FIBER; ++kf) {
            float fk[8];
#pragma unroll
            for (int i = 0; i < 8; ++i) fk[i] = s->Fs[m0 + i][kf];
#pragma unroll
            for (int j = 0; j < 6; ++j) {
                const int n = n0 + j;
                if (n >= D_FIBER) {
                    float w = s->Ws2[kf][n - D_FIBER];
#pragma unroll
                    for (int i = 0; i < 8; ++i)
                        acc[i][j] = fmaf(fk[i], w, acc[i][j]);
                }
            }
        }
#pragma unroll
        for (int j = 0; j < 6; ++j) {
            const int n = n0 + j;
            if (n >= D_FIBER) {
                const int nn = n - D_FIBER;
#pragma unroll
                for (int i = 0; i < 8; ++i) {
                    float v = acc[i][j] + s->b1s[nn];
                    // exact GELU: 0.5*x*(1+erf(x/sqrt(2)))
                    float g = 0.5f * v * (1.0f + erff(v * 0.70710678118654752f));
                    s->Hs[m0 + i][nn] = g;
                }
            }
        }
    }
    __syncthreads();

    // --- delta: h @ w2 + b2 -> softplus -> clip[0,1] ---
    if (tid < TM) {
        float a2 = b2[0];
#pragma unroll
        for (int n = 0; n < D_CONTROL; ++n)
            a2 = fmaf(s->Hs[tid][n], s->w2s[n], a2);
        float sp = (a2 > 20.0f) ? a2 : log1pf(expf(a2));
        sp = fminf(fmaxf(sp, 0.0f), 1.0f);
        delta_out[mblock + tid] = sp;
    }
}

// -------- EMA scan: field_t = 0.9*field_{t-1} + 0.1*delta_t, then clip + gate --------
#define SCAN_T 256

__global__ void cf_scan_kernel(const float* __restrict__ delta,
                               const float* __restrict__ lambda_gate,
                               float* __restrict__ field_out,
                               float* __restrict__ gate_out,
                               int S)
{
    const int b = blockIdx.x;
    const float* d = delta + (size_t)b * S;
    float* f = field_out + (size_t)b * S;
    float* g = gate_out + (size_t)b * S;
    const float lam = *lambda_gate;

    const int tid = threadIdx.x;
    const int per = S / SCAN_T;   // 16 for S=4096

    float vals[16];
    float accb = 0.0f;
    float accA = 1.0f;
    const int base = tid * per;
    for (int i = 0; i < per; ++i) {
        float x = d[base + i];
        vals[i] = x;
        accb = fmaf(0.9f, accb, 0.1f * x);
        accA *= 0.9f;
    }

    __shared__ float sa[SCAN_T];
    __shared__ float sb[SCAN_T];
    sa[tid] = accA;
    sb[tid] = accb;
    __syncthreads();

    // Hillis-Steele inclusive scan of (a,b) pairs: combine(left,right)=(al*ar, ar*bl+br)
    for (int off = 1; off < SCAN_T; off <<= 1) {
        float pa = 0.0f, pb = 0.0f;
        if (tid >= off) { pa = sa[tid - off]; pb = sb[tid - off]; }
        __syncthreads();
        if (tid >= off) {
            float ca = sa[tid], cb = sb[tid];
            sa[tid] = pa * ca;
            sb[tid] = fmaf(ca, pb, cb);
        }
        __syncthreads();
    }

    const float carry = (tid == 0) ? 0.0f : sb[tid - 1];

    float fld = carry;
    for (int i = 0; i < per; ++i) {
        fld = fmaf(0.9f, fld, 0.1f * vals[i]);
        float fc = fminf(fmaxf(fld, 0.0f), 10.0f);
        f[base + i] = fc;
        // sigmoid(-lam*fc) = 1/(1+exp(lam*fc))
        g[base + i] = 1.0f / (1.0f + expf(lam * fc));
    }
}

extern "C" void kernel_launch(void* const* d_in, const int* in_sizes, int n_in,
                              void* d_out, int out_size)
{
    const float* hidden = (const float*)d_in[0];
    const float* wf     = (const float*)d_in[1];
    const float* bf     = (const float*)d_in[2];
    const float* w1     = (const float*)d_in[3];
    const float* b1     = (const float*)d_in[4];
    const float* w2     = (const float*)d_in[5];
    const float* b2     = (const float*)d_in[6];
    const float* lam    = (const float*)d_in[7];

    const int Ntok = in_sizes[0] / D_MODEL;   // B*S
    float* out   = (float*)d_out;
    float* gate  = out;
    float* field = out + Ntok;
    float* delta = out + 2 * Ntok;
    float* fiber = out + 3 * Ntok;

    const int smem = (int)sizeof(SmemA);
    cudaFuncSetAttribute(cf_gemm_kernel, cudaFuncAttributeMaxDynamicSharedMemorySize, smem);

    cf_gemm_kernel<<<Ntok / TM, THREADS, smem>>>(hidden, wf, bf, w1, b1, w2, b2,
                                                 fiber, delta);

    const int S = SEQ_S;
    const int B = Ntok / S;
    cf_scan_kernel<<<B, SCAN_T>>>(delta, lam, field, gate, S);
}

// round 3
// speedup vs baseline: 1.0454x; 1.0454x over previous
#include <cuda_runtime.h>
#include <cuda_bf16.h>
#include <math.h>

// Problem constants (fixed shapes)
#define D_MODEL   512
#define D_FIBER   32
#define D_CONTROL 64
#define SEQ_S     4096

// GEMM tiling: 128 tokens x 96 cols per block, 128 threads, 8m x 12n per thread
#define TM 128
#define TN 96
#define TK 16
#define NKT (D_MODEL / TK)   // 32
#define THREADS 128
#define AS_STRIDE 132        // padded TM stride

typedef unsigned long long ull_t;

// packed fp32x2 FMA: d = a*b + d (per 32-bit lane). ptxas only emits FFMA2 via this.
#define FMA2(acc, a, b) \
    asm("fma.rn.f32x2 %0, %1, %2, %0;" : "+l"(acc) : "l"(a), "l"(b))
#define PACK_DUP(p, x) \
    asm("mov.b64 %0, {%1, %1};" : "=l"(p) : "r"(__float_as_uint(x)))
#define UNPACK2(lo, hi, v) \
    asm("mov.b64 {%0, %1}, %2;" : "=f"(lo), "=f"(hi) : "l"(v))

struct Smem {
    union {
        struct {
            float As[2][TK][AS_STRIDE];  // A chunk, [k][m]
            float Bs[2][TK][TN];         // B chunk, [k][n]
        } g;
        struct {
            float Fs[TM][33];            // fiber tile
            float Hs[TM][65];            // gelu(h) tile
        } e;
    } u;
    float Ws2[32][64];                   // w1 rows 512..543
    float b1s[64];
    float w2s[64];
    float bfs[32];
};

__global__ __launch_bounds__(THREADS, 2)
void cf_gemm_kernel(const float* __restrict__ hidden,
                    const float* __restrict__ wf,
                    const float* __restrict__ bf,
                    const float* __restrict__ w1,
                    const float* __restrict__ b1,
                    const float* __restrict__ w2,
                    const float* __restrict__ b2,
                    float* __restrict__ fiber_out,
                    float* __restrict__ delta_out)
{
    extern __shared__ char smem_raw[];
    Smem* s = reinterpret_cast<Smem*>(smem_raw);

    const int tid = threadIdx.x;
    const int mblock = blockIdx.x * TM;

    // 8 n-groups x 16 m-groups; each thread 8m x 12n (6 packed n-pairs)
    const int nt = tid & 7;
    const int mt = tid >> 3;
    const int n0 = nt * 12;
    const int m0 = mt * 8;

    // --- small constants / fiber-part weights ---
    if (tid < 64) {
        s->b1s[tid] = b1[tid];
        s->w2s[tid] = w2[tid];
    }
    if (tid < 32) s->bfs[tid] = bf[tid];
    for (int i = tid; i < 32 * 64; i += THREADS)
        s->Ws2[i >> 6][i & 63] = w1[(D_MODEL + (i >> 6)) * D_CONTROL + (i & 63)];

    // --- A load mapping: 512 float4 per chunk, 4 per thread ---
    const int arow = tid >> 2;          // 0..31, +j*32
    const int ac   = tid & 3;           // float4 col in chunk
    const float* aptr = hidden + (size_t)(mblock + arow) * D_MODEL + ac * 4;
    // --- B load mapping: 1536 floats, 12 per thread ---
    int kB[12], nB[12];
#pragma unroll
    for (int j = 0; j < 12; ++j) {
        int i = tid + j * THREADS;
        kB[j] = i / TN;
        nB[j] = i - kB[j] * TN;
    }

    // --- initial chunk into buffer 0 ---
    {
#pragma unroll
        for (int j = 0; j < 4; ++j) {
            float4 v = *(const float4*)(aptr + (size_t)j * 32 * D_MODEL);
            int kk = ac * 4, r = arow + j * 32;
            s->u.g.As[0][kk + 0][r] = v.x; s->u.g.As[0][kk + 1][r] = v.y;
            s->u.g.As[0][kk + 2][r] = v.z; s->u.g.As[0][kk + 3][r] = v.w;
        }
#pragma unroll
        for (int j = 0; j < 12; ++j) {
            int k = kB[j], n = nB[j];
            s->u.g.Bs[0][k][n] = (n < D_FIBER) ? wf[k * D_FIBER + n]
                                               : w1[k * D_CONTROL + (n - D_FIBER)];
        }
    }
    __syncthreads();

    ull_t acc[8][6];
#pragma unroll
    for (int i = 0; i < 8; ++i)
#pragma unroll
        for (int j = 0; j < 6; ++j) acc[i][j] = 0ull;

    // --- main K loop, double buffered ---
    for (int kt = 0; kt < NKT; ++kt) {
        const int cur = kt & 1;
        float4 av[4];
        float bv[12];
        const bool pref = (kt + 1) < NKT;
        if (pref) {
            const int k0n = (kt + 1) * TK;
#pragma unroll
            for (int j = 0; j < 4; ++j)
                av[j] = *(const float4*)(aptr + (size_t)j * 32 * D_MODEL + k0n);
#pragma unroll
            for (int j = 0; j < 12; ++j) {
                int k = k0n + kB[j], n = nB[j];
                bv[j] = (n < D_FIBER) ? wf[k * D_FIBER + n]
                                      : w1[k * D_CONTROL + (n - D_FIBER)];
            }
        }

#pragma unroll
        for (int k = 0; k < TK; ++k) {
            const float4* ap = (const float4*)&s->u.g.As[cur][k][m0];
            float4 a0 = ap[0];
            float4 a1 = ap[1];
            ull_t ad[8];
            PACK_DUP(ad[0], a0.x); PACK_DUP(ad[1], a0.y);
            PACK_DUP(ad[2], a0.z); PACK_DUP(ad[3], a0.w);
            PACK_DUP(ad[4], a1.x); PACK_DUP(ad[5], a1.y);
            PACK_DUP(ad[6], a1.z); PACK_DUP(ad[7], a1.w);
            const ulonglong2* bq = (const ulonglong2*)&s->u.g.Bs[cur][k][n0];
            ulonglong2 b01 = bq[0], b23 = bq[1], b45 = bq[2];
            ull_t bp[6] = {b01.x, b01.y, b23.x, b23.y, b45.x, b45.y};
#pragma unroll
            for (int i = 0; i < 8; ++i)
#pragma unroll
                for (int j = 0; j < 6; ++j)
                    FMA2(acc[i][j], ad[i], bp[j]);
        }

        if (pref) {
            const int nxt = cur ^ 1;
#pragma unroll
            for (int j = 0; j < 4; ++j) {
                int kk = ac * 4, r = arow + j * 32;
                s->u.g.As[nxt][kk + 0][r] = av[j].x; s->u.g.As[nxt][kk + 1][r] = av[j].y;
                s->u.g.As[nxt][kk + 2][r] = av[j].z; s->u.g.As[nxt][kk + 3][r] = av[j].w;
            }
#pragma unroll
            for (int j = 0; j < 12; ++j) s->u.g.Bs[nxt][kB[j]][nB[j]] = bv[j];
        }
        __syncthreads();
    }

    // --- fiber epilogue (cols n < 32): bias, write out + stash in smem ---
#pragma unroll
    for (int jp = 0; jp < 6; ++jp) {
        const int n = n0 + 2 * jp;
        if (n < D_FIBER) {
            const float blo = s->bfs[n], bhi = s->bfs[n + 1];
#pragma unroll
            for (int i = 0; i < 8; ++i) {
                float lo, hi;
                UNPACK2(lo, hi, acc[i][jp]);
                lo += blo; hi += bhi;
                s->u.e.Fs[m0 + i][n] = lo;
                s->u.e.Fs[m0 + i][n + 1] = hi;
                float* fo = fiber_out + (size_t)(mblock + m0 + i) * D_FIBER + n;
                fo[0] = lo; fo[1] = hi;
            }
        }
    }
    __syncthreads();

    // --- h cols (n >= 32): + fiber @ w1[512:544] (packed), bias, exact GELU ---
    if (n0 + 11 >= D_FIBER) {
        for (int kf = 0; kf < D_FIBER; ++kf) {
            ull_t fkd[8];
#pragma unroll
            for (int i = 0; i < 8; ++i) {
                float fv = s->u.e.Fs[m0 + i][kf];
                PACK_DUP(fkd[i], fv);
            }
#pragma unroll
            for (int jp = 0; jp < 6; ++jp) {
                const int n = n0 + 2 * jp;
                if (n >= D_FIBER) {
                    ull_t w = *(const ull_t*)&s->Ws2[kf][n - D_FIBER];
#pragma unroll
                    for (int i = 0; i < 8; ++i)
                        FMA2(acc[i][jp], fkd[i], w);
                }
            }
        }
#pragma unroll
        for (int jp = 0; jp < 6; ++jp) {
            const int n = n0 + 2 * jp;
            if (n >= D_FIBER) {
                const int nn = n - D_FIBER;
                const float blo = s->b1s[nn], bhi = s->b1s[nn + 1];
#pragma unroll
                for (int i = 0; i < 8; ++i) {
                    float lo, hi;
                    UNPACK2(lo, hi, acc[i][jp]);
                    lo += blo; hi += bhi;
                    float glo = 0.5f * lo * (1.0f + erff(lo * 0.70710678118654752f));
                    float ghi = 0.5f * hi * (1.0f + erff(hi * 0.70710678118654752f));
                    s->u.e.Hs[m0 + i][nn] = glo;
                    s->u.e.Hs[m0 + i][nn + 1] = ghi;
                }
            }
        }
    }
    __syncthreads();

    // --- delta: h @ w2 + b2 -> softplus -> clip[0,1] ---
    {
        float a2 = b2[0];
#pragma unroll
        for (int n = 0; n < D_CONTROL; ++n)
            a2 = fmaf(s->u.e.Hs[tid][n], s->w2s[n], a2);
        float sp = (a2 > 20.0f) ? a2 : log1pf(expf(a2));
        sp = fminf(fmaxf(sp, 0.0f), 1.0f);
        delta_out[mblock + tid] = sp;
    }
}

// -------- EMA scan: field_t = 0.9*field_{t-1} + 0.1*delta_t, clip + gate --------
// All combine decay factors are compile-time constants (equal segment lengths):
#define C8   0.43046721f
#define C16  0.18530201888518410f
#define C32  0.034336838202925124f
#define C64  0.0011790184577738583f
#define C128 1.3900845237714473e-06f
#define C256 1.9323349832288915e-12f
#define C512 3.7339184874102004e-24f

#define SCAN_T 512

__global__ void cf_scan_kernel(const float* __restrict__ delta,
                               const float* __restrict__ lambda_gate,
                               float* __restrict__ field_out,
                               float* __restrict__ gate_out,
                               int S)
{
    const int b = blockIdx.x;
    const float* d = delta + (size_t)b * S;
    float* f = field_out + (size_t)b * S;
    float* g = gate_out + (size_t)b * S;
    const float lam = *lambda_gate;

    const int tid = threadIdx.x;
    const int lane = tid & 31;
    const int warp = tid >> 5;
    const int base = tid * 8;

    // serial reduce of own 8-element segment
    float4 v0 = *(const float4*)(d + base);
    float4 v1 = *(const float4*)(d + base + 4);
    float vals[8] = {v0.x, v0.y, v0.z, v0.w, v1.x, v1.y, v1.z, v1.w};
    float bacc = 0.0f;
#pragma unroll
    for (int i = 0; i < 8; ++i) bacc = fmaf(0.9f, bacc, 0.1f * vals[i]);

    // warp inclusive scan with geometric decay constants
    float inc = bacc;
    {
        float p;
        p = __shfl_up_sync(0xffffffffu, inc, 1);  if (lane >= 1)  inc = fmaf(C8,   p, inc);
        p = __shfl_up_sync(0xffffffffu, inc, 2);  if (lane >= 2)  inc = fmaf(C16,  p, inc);
        p = __shfl_up_sync(0xffffffffu, inc, 4);  if (lane >= 4)  inc = fmaf(C32,  p, inc);
        p = __shfl_up_sync(0xffffffffu, inc, 8);  if (lane >= 8)  inc = fmaf(C64,  p, inc);
        p = __shfl_up_sync(0xffffffffu, inc, 16); if (lane >= 16) inc = fmaf(C128, p, inc);
    }
    float lane_excl = __shfl_up_sync(0xffffffffu, inc, 1);
    if (lane == 0) lane_excl = 0.0f;

    __shared__ float ws[16];   // per-warp inclusive sums
    __shared__ float wc[16];   // inclusive scan of warp sums
    if (lane == 31) ws[warp] = inc;
    __syncthreads();
    if (tid < 16) {
        float w = ws[tid];
        float p;
        p = __shfl_up_sync(0x0000ffffu, w, 1); if (tid >= 1) w = fmaf(C256, p, w);
        p = __shfl_up_sync(0x0000ffffu, w, 2); if (tid >= 2) w = fmaf(C512, p, w);
        // 0.9^1024, 0.9^2048 underflow fp32 -> contributions are exactly 0
        wc[tid] = w;
    }
    __syncthreads();

    // decay for elements preceding this thread within its warp: 0.9^(8*lane)
    float dec = 1.0f;
    if (lane & 1)  dec *= C8;
    if (lane & 2)  dec *= C16;
    if (lane & 4)  dec *= C32;
    if (lane & 8)  dec *= C64;
    if (lane & 16) dec *= C128;

    const float wcarry = (warp == 0) ? 0.0f : wc[warp - 1];
    float fld = fmaf(dec, wcarry, lane_excl);

    float fo[8], go[8];
#pragma unroll
    for (int i = 0; i < 8; ++i) {
        fld = fmaf(0.9f, fld, 0.1f * vals[i]);
        float fc = fminf(fmaxf(fld, 0.0f), 10.0f);
        fo[i] = fc;
        go[i] = 1.0f / (1.0f + expf(lam * fc));
    }
    *(float4*)(f + base)     = make_float4(fo[0], fo[1], fo[2], fo[3]);
    *(float4*)(f + base + 4) = make_float4(fo[4], fo[5], fo[6], fo[7]);
    *(float4*)(g + base)     = make_float4(go[0], go[1], go[2], go[3]);
    *(float4*)(g + base + 4) = make_float4(go[4], go[5], go[6], go[7]);
}

extern "C" void kernel_launch(void* const* d_in, const int* in_sizes, int n_in,
                              void* d_out, int out_size)
{
    const float* hidden = (const float*)d_in[0];
    const float* wf     = (const float*)d_in[1];
    const float* bf     = (const float*)d_in[2];
    const float* w1     = (const float*)d_in[3];
    const float* b1     = (const float*)d_in[4];
    const float* w2     = (const float*)d_in[5];
    const float* b2     = (const float*)d_in[6];
    const float* lam    = (const float*)d_in[7];

    const int Ntok = in_sizes[0] / D_MODEL;   // B*S = 32768
    float* out   = (float*)d_out;
    float* gate  = out;
    float* field = out + Ntok;
    float* delta = out + 2 * Ntok;
    float* fiber = out + 3 * Ntok;

    const int smem = (int)sizeof(Smem);
    cudaFuncSetAttribute(cf_gemm_kernel, cudaFuncAttributeMaxDynamicSharedMemorySize, smem);

    cf_gemm_kernel<<<Ntok / TM, THREADS, smem>>>(hidden, wf, bf, w1, b1, w2, b2,
                                                 fiber, delta);

    const int S = SEQ_S;
    const int B = Ntok / S;
    cf_scan_kernel<<<B, SCAN_T>>>(delta, lam, field, gate, S);
}

// round 7
// speedup vs baseline: 1.4700x; 1.4062x over previous
#include <cuda_runtime.h>
#include <cuda_bf16.h>
#include <math.h>
#include <stdint.h>
#include <string.h>

#define D_MODEL 512
#define SEQ_S   4096
#define TM      128
#define KC      64
#define NCHUNK  8
#define THREADS 256

#define ASTR 144            // bytes per A/B smem row (72 bf16)
#define DSTR 104            // floats per D-tile row

// smem byte offsets
#define OFF_AH  0           // 128*144 = 18432
#define OFF_AL  18432
#define OFF_B   36864       // 2 bufs x (hi 13824 + lo 13824) = 55296
#define BBUF    27648
#define BLO     13824
#define OFF_WS2 92160       // fp32 [32][64] = 8192
#define OFF_BFS 100352
#define OFF_B1S 100480
#define OFF_W2S 100736
#define SMEM_BYTES 102016

// pre-split combined weights [n=96][k=512] bf16 hi/lo
__device__ __align__(16) __nv_bfloat16 g_Bhi[96 * 512];
__device__ __align__(16) __nv_bfloat16 g_Blo[96 * 512];

// ---------------- helpers ----------------
__device__ __forceinline__ uint32_t b2u(__nv_bfloat162 h) {
    uint32_t u; memcpy(&u, &h, 4); return u;
}
__device__ __forceinline__ void cp16(uint32_t dst, const void* src) {
    asm volatile("cp.async.cg.shared.global [%0], [%1], 16;" :: "r"(dst), "l"(src));
}
#define CP_COMMIT() asm volatile("cp.async.commit_group;" ::: "memory")
#define CP_WAIT0()  asm volatile("cp.async.wait_group 0;" ::: "memory")
#define CP_WAIT1()  asm volatile("cp.async.wait_group 1;" ::: "memory")

__device__ __forceinline__ uint32_t cvta_smem(const void* p) {
    uint32_t a;
    asm("{ .reg .u64 t; cvta.to.shared.u64 t, %1; cvt.u32.u64 %0, t; }" : "=r"(a) : "l"(p));
    return a;
}
__device__ __forceinline__ void mma16816(float* c, const uint32_t* a, const uint32_t* b) {
    asm volatile("mma.sync.aligned.m16n8k16.row.col.f32.bf16.bf16.f32 "
        "{%0,%1,%2,%3}, {%4,%5,%6,%7}, {%8,%9}, {%0,%1,%2,%3};"
        : "+f"(c[0]), "+f"(c[1]), "+f"(c[2]), "+f"(c[3])
        : "r"(a[0]), "r"(a[1]), "r"(a[2]), "r"(a[3]), "r"(b[0]), "r"(b[1]));
}
// split 4 floats into bf16 hi pair-pack + residual pair-pack
__device__ __forceinline__ void split4(float4 v, uint2& hi, uint2& lo) {
    __nv_bfloat162 hp = __floats2bfloat162_rn(v.x, v.y);   // .x -> low half
    __nv_bfloat162 hq = __floats2bfloat162_rn(v.z, v.w);
    float e0 = v.x - __bfloat162float(hp.x);
    float e1 = v.y - __bfloat162float(hp.y);
    float e2 = v.z - __bfloat162float(hq.x);
    float e3 = v.w - __bfloat162float(hq.y);
    hi = make_uint2(b2u(hp), b2u(hq));
    lo = make_uint2(b2u(__floats2bfloat162_rn(e0, e1)),
                    b2u(__floats2bfloat162_rn(e2, e3)));
}

// ---------------- prelude: split combined weights ----------------
__global__ void cf_prep_kernel(const float* __restrict__ wf, const float* __restrict__ w1)
{
    int t = blockIdx.x * blockDim.x + threadIdx.x;
    int NT = gridDim.x * blockDim.x;
    for (int i = t; i < 96 * 512; i += NT) {
        int n = i >> 9, k = i & 511;
        float v = (n < 32) ? wf[k * 32 + n] : w1[k * 64 + (n - 32)];
        __nv_bfloat16 h = __float2bfloat16_rn(v);
        g_Bhi[i] = h;
        g_Blo[i] = __float2bfloat16_rn(v - __bfloat162float(h));
    }
}

// ---------------- main fused kernel ----------------
__global__ __launch_bounds__(THREADS)
void cf_mma_kernel(const float* __restrict__ hidden,
                   const float* __restrict__ bf,
                   const float* __restrict__ b1,
                   const float* __restrict__ w1,
                   const float* __restrict__ w2,
                   const float* __restrict__ b2,
                   float* __restrict__ fiber_out,
                   float* __restrict__ delta_out)
{
    extern __shared__ char base[];
    const uint32_t sbase = cvta_smem(base);
    float* Dfp = (float*)base;

    const int tid = threadIdx.x;
    const int w   = tid >> 5;
    const int l   = tid & 31;
    const int mblock = blockIdx.x * TM;

    const int m0w = (w & 3) * 32;     // warp M base
    const int n0w = (w >> 2) * 48;    // warp N base
    const int g   = l >> 2;           // 0..7
    const int tg4 = (l & 3) * 4;      // byte offset of k-pair

    // constants + Ws2 (fp32 fiber-part of w1, rows 512..543 -> [kf][64])
    if (tid < 64) {
        ((float*)(base + OFF_B1S))[tid] = b1[tid];
        ((float*)(base + OFF_W2S))[tid] = w2[tid];
    }
    if (tid < 32) ((float*)(base + OFF_BFS))[tid] = bf[tid];
    {
        float* Wp = (float*)(base + OFF_WS2);
        for (int i = tid; i < 32 * 64; i += THREADS) Wp[i] = w1[512 * 64 + i];
    }

    // B chunk 0 via cp.async: 1536 x 16B (768 hi + 768 lo)
    // FIX: exact r arithmetic (768 is not a pow2 -> no & mask!)
#pragma unroll
    for (int t = 0; t < 6; ++t) {
        int isLo = (t >= 3);
        int r = tid + (t - 3 * isLo) * 256;   // 0..767
        int n = r >> 3, q = r & 7;
        const char* src = (const char*)(isLo ? g_Blo : g_Bhi) + n * 1024 + q * 16;
        cp16(sbase + OFF_B + isLo * BLO + n * ASTR + q * 16, src);
    }
    CP_COMMIT();

    // A chunk 0: LDG + split in regs
    const int arow = tid >> 1;
    const int akh  = (tid & 1) * 32;
    const float* asrc = hidden + (size_t)(mblock + arow) * D_MODEL + akh;
    uint2 ah[8], al[8];
#pragma unroll
    for (int j = 0; j < 8; ++j)
        split4(*(const float4*)(asrc + j * 4), ah[j], al[j]);

    float acc[2][6][4];
#pragma unroll
    for (int mt = 0; mt < 2; ++mt)
#pragma unroll
        for (int nt = 0; nt < 6; ++nt)
#pragma unroll
            for (int q = 0; q < 4; ++q) acc[mt][nt][q] = 0.0f;

    // ---------------- main K loop ----------------
    for (int c = 0; c < NCHUNK; ++c) {
        const int buf = c & 1;
        __syncthreads();   // prior chunk compute done

        // STS A (hi/lo)
        {
            char* ad = base + arow * ASTR + akh * 2;
#pragma unroll
            for (int j = 0; j < 8; ++j) {
                *(uint2*)(ad + OFF_AH + j * 8) = ah[j];
                *(uint2*)(ad + OFF_AL + j * 8) = al[j];
            }
        }
        if (c + 1 < NCHUNK) {
#pragma unroll
            for (int t = 0; t < 6; ++t) {
                int isLo = (t >= 3);
                int r = tid + (t - 3 * isLo) * 256;   // FIX: 0..767 exact
                int n = r >> 3, q = r & 7;
                const char* src = (const char*)(isLo ? g_Blo : g_Bhi)
                                  + n * 1024 + (c + 1) * 128 + q * 16;
                cp16(sbase + OFF_B + (buf ^ 1) * BBUF + isLo * BLO + n * ASTR + q * 16, src);
            }
            CP_COMMIT();
            CP_WAIT1();
        } else {
            CP_WAIT0();
        }
        __syncthreads();

        // prefetch A for next chunk
        if (c + 1 < NCHUNK) {
            const float* src = asrc + (c + 1) * KC;
#pragma unroll
            for (int j = 0; j < 8; ++j)
                split4(*(const float4*)(src + j * 4), ah[j], al[j]);
        }

        // compute chunk c: fragments via direct LDS.32
        {
            const char* Bb = base + OFF_B + buf * BBUF;
#pragma unroll
            for (int ks = 0; ks < 4; ++ks) {
                uint32_t Ah[2][4], Al[2][4], Bh[6][2], Bl[6][2];
#pragma unroll
                for (int mt = 0; mt < 2; ++mt) {
                    const char* pa = base + (m0w + mt * 16 + g) * ASTR + ks * 32 + tg4;
                    Ah[mt][0] = *(const uint32_t*)(pa + OFF_AH);
                    Ah[mt][1] = *(const uint32_t*)(pa + OFF_AH + 8 * ASTR);
                    Ah[mt][2] = *(const uint32_t*)(pa + OFF_AH + 16);
                    Ah[mt][3] = *(const uint32_t*)(pa + OFF_AH + 8 * ASTR + 16);
                    Al[mt][0] = *(const uint32_t*)(pa + OFF_AL);
                    Al[mt][1] = *(const uint32_t*)(pa + OFF_AL + 8 * ASTR);
                    Al[mt][2] = *(const uint32_t*)(pa + OFF_AL + 16);
                    Al[mt][3] = *(const uint32_t*)(pa + OFF_AL + 8 * ASTR + 16);
                }
#pragma unroll
                for (int nt = 0; nt < 6; ++nt) {
                    const char* pb = Bb + (n0w + nt * 8 + g) * ASTR + ks * 32 + tg4;
                    Bh[nt][0] = *(const uint32_t*)(pb);
                    Bh[nt][1] = *(const uint32_t*)(pb + 16);
                    Bl[nt][0] = *(const uint32_t*)(pb + BLO);
                    Bl[nt][1] = *(const uint32_t*)(pb + BLO + 16);
                }
#pragma unroll
                for (int mt = 0; mt < 2; ++mt)
#pragma unroll
                    for (int nt = 0; nt < 6; ++nt) {
                        mma16816(acc[mt][nt], Ah[mt], Bh[nt]);
                        mma16816(acc[mt][nt], Ah[mt], Bl[nt]);
                        mma16816(acc[mt][nt], Al[mt], Bh[nt]);
                    }
            }
        }
    }
    __syncthreads();

    // ---------------- D store ----------------
#pragma unroll
    for (int mt = 0; mt < 2; ++mt)
#pragma unroll
        for (int nt = 0; nt < 6; ++nt) {
            int r = m0w + mt * 16 + (l >> 2);
            int cb = n0w + nt * 8 + 2 * (l & 3);
            Dfp[r * DSTR + cb]           = acc[mt][nt][0];
            Dfp[r * DSTR + cb + 1]       = acc[mt][nt][1];
            Dfp[(r + 8) * DSTR + cb]     = acc[mt][nt][2];
            Dfp[(r + 8) * DSTR + cb + 1] = acc[mt][nt][3];
        }
    __syncthreads();

    // ---------------- fiber: bias, STG, write biased back to D ----------------
    {
        int rq = tid >> 3, cq = (tid & 7) * 4;
        float4 bb = *(float4*)((float*)(base + OFF_BFS) + cq);
#pragma unroll
        for (int i = 0; i < 4; ++i) {
            int r = rq + i * 32;
            float4 dv = *(float4*)&Dfp[r * DSTR + cq];
            dv.x += bb.x; dv.y += bb.y; dv.z += bb.z; dv.w += bb.w;
            *(float4*)(fiber_out + (size_t)(mblock + r) * 32 + cq) = dv;
            *(float4*)&Dfp[r * DSTR + cq] = dv;
        }
    }
    __syncthreads();

    // ---------------- pass 2: h += fiber @ Ws2, bias, GELU (fp32 FFMA) ----------------
    {
        const int m  = tid >> 1;
        const int nb = (tid & 1) * 32;
        float fib[32];
#pragma unroll
        for (int q = 0; q < 8; ++q)
            *(float4*)&fib[q * 4] = *(float4*)&Dfp[m * DSTR + q * 4];

        float hacc[32];
#pragma unroll
        for (int q = 0; q < 32; ++q) hacc[q] = 0.0f;

        const float* Wp = (const float*)(base + OFF_WS2);
#pragma unroll
        for (int kf = 0; kf < 32; ++kf) {
            float fv = fib[kf];
#pragma unroll
            for (int q = 0; q < 8; ++q) {
                float4 wv = *(const float4*)&Wp[kf * 64 + nb + q * 4];
                hacc[q * 4 + 0] = fmaf(fv, wv.x, hacc[q * 4 + 0]);
                hacc[q * 4 + 1] = fmaf(fv, wv.y, hacc[q * 4 + 1]);
                hacc[q * 4 + 2] = fmaf(fv, wv.z, hacc[q * 4 + 2]);
                hacc[q * 4 + 3] = fmaf(fv, wv.w, hacc[q * 4 + 3]);
            }
        }
        const float* b1p = (const float*)(base + OFF_B1S);
        const float is2 = 0.70710678118654752f;
#pragma unroll
        for (int q = 0; q < 32; ++q) {
            float x = Dfp[m * DSTR + 32 + nb + q] + hacc[q] + b1p[nb + q];
            Dfp[m * DSTR + 32 + nb + q] = 0.5f * x * (1.0f + erff(x * is2));
        }
    }
    __syncthreads();

    // ---------------- delta: h @ w2 + b2 -> softplus -> clip ----------------
    if (tid < TM) {
        float a2 = b2[0];
        const float* w2p = (const float*)(base + OFF_W2S);
#pragma unroll
        for (int q = 0; q < 16; ++q) {
            float4 h4 = *(float4*)&Dfp[tid * DSTR + 32 + q * 4];
            float4 w4 = *(const float4*)&w2p[q * 4];
            a2 = fmaf(h4.x, w4.x, a2);
            a2 = fmaf(h4.y, w4.y, a2);
            a2 = fmaf(h4.z, w4.z, a2);
            a2 = fmaf(h4.w, w4.w, a2);
        }
        float sp = (a2 > 20.0f) ? a2 : log1pf(expf(a2));
        sp = fminf(fmaxf(sp, 0.0f), 1.0f);
        delta_out[mblock + tid] = sp;
    }
}

// -------- EMA scan (unchanged, known-good) --------
#define C8   0.43046721f
#define C16  0.18530201888518410f
#define C32  0.034336838202925124f
#define C64  0.0011790184577738583f
#define C128 1.3900845237714473e-06f
#define C256 1.9323349832288915e-12f
#define C512 3.7339184874102004e-24f
#define SCAN_T 512

__global__ void cf_scan_kernel(const float* __restrict__ delta,
                               const float* __restrict__ lambda_gate,
                               float* __restrict__ field_out,
                               float* __restrict__ gate_out,
                               int S)
{
    const int b = blockIdx.x;
    const float* d = delta + (size_t)b * S;
    float* f = field_out + (size_t)b * S;
    float* g = gate_out + (size_t)b * S;
    const float lam = *lambda_gate;

    const int tid = threadIdx.x;
    const int lane = tid & 31;
    const int warp = tid >> 5;
    const int base = tid * 8;

    float4 v0 = *(const float4*)(d + base);
    float4 v1 = *(const float4*)(d + base + 4);
    float vals[8] = {v0.x, v0.y, v0.z, v0.w, v1.x, v1.y, v1.z, v1.w};
    float bacc = 0.0f;
#pragma unroll
    for (int i = 0; i < 8; ++i) bacc = fmaf(0.9f, bacc, 0.1f * vals[i]);

    float inc = bacc;
    {
        float p;
        p = __shfl_up_sync(0xffffffffu, inc, 1);  if (lane >= 1)  inc = fmaf(C8,   p, inc);
        p = __shfl_up_sync(0xffffffffu, inc, 2);  if (lane >= 2)  inc = fmaf(C16,  p, inc);
        p = __shfl_up_sync(0xffffffffu, inc, 4);  if (lane >= 4)  inc = fmaf(C32,  p, inc);
        p = __shfl_up_sync(0xffffffffu, inc, 8);  if (lane >= 8)  inc = fmaf(C64,  p, inc);
        p = __shfl_up_sync(0xffffffffu, inc, 16); if (lane >= 16) inc = fmaf(C128, p, inc);
    }
    float lane_excl = __shfl_up_sync(0xffffffffu, inc, 1);
    if (lane == 0) lane_excl = 0.0f;

    __shared__ float ws[16];
    __shared__ float wc[16];
    if (lane == 31) ws[warp] = inc;
    __syncthreads();
    if (tid < 16) {
        float wv = ws[tid];
        float p;
        p = __shfl_up_sync(0x0000ffffu, wv, 1); if (tid >= 1) wv = fmaf(C256, p, wv);
        p = __shfl_up_sync(0x0000ffffu, wv, 2); if (tid >= 2) wv = fmaf(C512, p, wv);
        wc[tid] = wv;
    }
    __syncthreads();

    float dec = 1.0f;
    if (lane & 1)  dec *= C8;
    if (lane & 2)  dec *= C16;
    if (lane & 4)  dec *= C32;
    if (lane & 8)  dec *= C64;
    if (lane & 16) dec *= C128;

    const float wcarry = (warp == 0) ? 0.0f : wc[warp - 1];
    float fld = fmaf(dec, wcarry, lane_excl);

    float fo[8], go[8];
#pragma unroll
    for (int i = 0; i < 8; ++i) {
        fld = fmaf(0.9f, fld, 0.1f * vals[i]);
        float fc = fminf(fmaxf(fld, 0.0f), 10.0f);
        fo[i] = fc;
        go[i] = 1.0f / (1.0f + expf(lam * fc));
    }
    *(float4*)(f + base)     = make_float4(fo[0], fo[1], fo[2], fo[3]);
    *(float4*)(f + base + 4) = make_float4(fo[4], fo[5], fo[6], fo[7]);
    *(float4*)(g + base)     = make_float4(go[0], go[1], go[2], go[3]);
    *(float4*)(g + base + 4) = make_float4(go[4], go[5], go[6], go[7]);
}

extern "C" void kernel_launch(void* const* d_in, const int* in_sizes, int n_in,
                              void* d_out, int out_size)
{
    const float* hidden = (const float*)d_in[0];
    const float* wf     = (const float*)d_in[1];
    const float* bf     = (const float*)d_in[2];
    const float* w1     = (const float*)d_in[3];
    const float* b1     = (const float*)d_in[4];
    const float* w2     = (const float*)d_in[5];
    const float* b2     = (const float*)d_in[6];
    const float* lam    = (const float*)d_in[7];

    const int Ntok = in_sizes[0] / D_MODEL;   // 32768
    float* out   = (float*)d_out;
    float* gate  = out;
    float* field = out + Ntok;
    float* delta = out + 2 * Ntok;
    float* fiber = out + 3 * Ntok;

    cudaFuncSetAttribute(cf_mma_kernel, cudaFuncAttributeMaxDynamicSharedMemorySize, SMEM_BYTES);

    cf_prep_kernel<<<64, 256>>>(wf, w1);
    cf_mma_kernel<<<Ntok / TM, THREADS, SMEM_BYTES>>>(hidden, bf, b1, w1, w2, b2, fiber, delta);
    cf_scan_kernel<<<Ntok / SEQ_S, SCAN_T>>>(delta, lam, field, gate, SEQ_S);
}

// round 8
// speedup vs baseline: 1.5290x; 1.0402x over previous
#include <cuda_runtime.h>
#include <cuda_bf16.h>
#include <math.h>
#include <stdint.h>
#include <string.h>

#define D_MODEL 512
#define SEQ_S   4096
#define TM      128
#define KC      64
#define NCHUNK  8
#define THREADS 256

#define ASTR 144            // bytes per A/B smem row (72 bf16)
#define DSTR 104            // floats per D-tile row

// smem byte offsets
#define OFF_AH  0           // 128*144 = 18432
#define OFF_AL  18432
#define OFF_B   36864       // 2 bufs x (hi 13824 + lo 13824) = 55296
#define BBUF    27648
#define BLO     13824
#define OFF_WS2 92160       // fp32 [32][64] = 8192
#define OFF_BFS 100352
#define OFF_B1S 100480
#define OFF_W2S 100736
#define SMEM_BYTES 100992   // 2 CTAs/SM: 2x100992 = 197.2KB <= 228KB

// pre-split combined weights [n=96][k=512] bf16 hi/lo
__device__ __align__(16) __nv_bfloat16 g_Bhi[96 * 512];
__device__ __align__(16) __nv_bfloat16 g_Blo[96 * 512];

// ---------------- helpers ----------------
__device__ __forceinline__ uint32_t b2u(__nv_bfloat162 h) {
    uint32_t u; memcpy(&u, &h, 4); return u;
}
__device__ __forceinline__ void cp16(uint32_t dst, const void* src) {
    asm volatile("cp.async.cg.shared.global [%0], [%1], 16;" :: "r"(dst), "l"(src));
}
#define CP_COMMIT() asm volatile("cp.async.commit_group;" ::: "memory")
#define CP_WAIT0()  asm volatile("cp.async.wait_group 0;" ::: "memory")
#define CP_WAIT1()  asm volatile("cp.async.wait_group 1;" ::: "memory")

__device__ __forceinline__ uint32_t cvta_smem(const void* p) {
    uint32_t a;
    asm("{ .reg .u64 t; cvta.to.shared.u64 t, %1; cvt.u32.u64 %0, t; }" : "=r"(a) : "l"(p));
    return a;
}
__device__ __forceinline__ void mma16816(float* c, const uint32_t* a, const uint32_t* b) {
    asm volatile("mma.sync.aligned.m16n8k16.row.col.f32.bf16.bf16.f32 "
        "{%0,%1,%2,%3}, {%4,%5,%6,%7}, {%8,%9}, {%0,%1,%2,%3};"
        : "+f"(c[0]), "+f"(c[1]), "+f"(c[2]), "+f"(c[3])
        : "r"(a[0]), "r"(a[1]), "r"(a[2]), "r"(a[3]), "r"(b[0]), "r"(b[1]));
}
// split 4 floats into bf16 hi pair-pack + residual pair-pack
__device__ __forceinline__ void split4(float4 v, uint2& hi, uint2& lo) {
    __nv_bfloat162 hp = __floats2bfloat162_rn(v.x, v.y);   // .x -> low half
    __nv_bfloat162 hq = __floats2bfloat162_rn(v.z, v.w);
    float e0 = v.x - __bfloat162float(hp.x);
    float e1 = v.y - __bfloat162float(hp.y);
    float e2 = v.z - __bfloat162float(hq.x);
    float e3 = v.w - __bfloat162float(hq.y);
    hi = make_uint2(b2u(hp), b2u(hq));
    lo = make_uint2(b2u(__floats2bfloat162_rn(e0, e1)),
                    b2u(__floats2bfloat162_rn(e2, e3)));
}

// ---------------- prelude: split combined weights (one elt/thread) ----------------
__global__ void cf_prep_kernel(const float* __restrict__ wf, const float* __restrict__ w1)
{
    int i = blockIdx.x * blockDim.x + threadIdx.x;   // grid 192 x 256 = 49152 exactly
    int n = i >> 9, k = i & 511;
    float v = (n < 32) ? wf[k * 32 + n] : w1[k * 64 + (n - 32)];
    __nv_bfloat16 h = __float2bfloat16_rn(v);
    g_Bhi[i] = h;
    g_Blo[i] = __float2bfloat16_rn(v - __bfloat162float(h));
}

// ---------------- main fused kernel ----------------
__global__ __launch_bounds__(THREADS, 2)
void cf_mma_kernel(const float* __restrict__ hidden,
                   const float* __restrict__ bf,
                   const float* __restrict__ b1,
                   const float* __restrict__ w1,
                   const float* __restrict__ w2,
                   const float* __restrict__ b2,
                   float* __restrict__ fiber_out,
                   float* __restrict__ delta_out)
{
    extern __shared__ char base[];
    const uint32_t sbase = cvta_smem(base);
    float* Dfp = (float*)base;

    const int tid = threadIdx.x;
    const int w   = tid >> 5;
    const int l   = tid & 31;
    const int mblock = blockIdx.x * TM;

    const int m0w = (w & 3) * 32;     // warp M base
    const int n0w = (w >> 2) * 48;    // warp N base
    const int g   = l >> 2;           // 0..7
    const int tg4 = (l & 3) * 4;      // byte offset of k-pair

    // constants + Ws2 (fp32 fiber-part of w1, rows 512..543 -> [kf][64])
    if (tid < 64) {
        ((float*)(base + OFF_B1S))[tid] = b1[tid];
        ((float*)(base + OFF_W2S))[tid] = w2[tid];
    }
    if (tid < 32) ((float*)(base + OFF_BFS))[tid] = bf[tid];
    {
        float* Wp = (float*)(base + OFF_WS2);
        for (int i = tid; i < 32 * 64; i += THREADS) Wp[i] = w1[512 * 64 + i];
    }

    // B chunk 0 via cp.async: 1536 x 16B (768 hi + 768 lo)
#pragma unroll
    for (int t = 0; t < 6; ++t) {
        int isLo = (t >= 3);
        int r = tid + (t - 3 * isLo) * 256;   // 0..767
        int n = r >> 3, q = r & 7;
        const char* src = (const char*)(isLo ? g_Blo : g_Bhi) + n * 1024 + q * 16;
        cp16(sbase + OFF_B + isLo * BLO + n * ASTR + q * 16, src);
    }
    CP_COMMIT();

    // A chunk 0: LDG + split in regs
    const int arow = tid >> 1;
    const int akh  = (tid & 1) * 32;
    const float* asrc = hidden + (size_t)(mblock + arow) * D_MODEL + akh;
    uint2 ah[8], al[8];
#pragma unroll
    for (int j = 0; j < 8; ++j)
        split4(*(const float4*)(asrc + j * 4), ah[j], al[j]);

    float acc[2][6][4];
#pragma unroll
    for (int mt = 0; mt < 2; ++mt)
#pragma unroll
        for (int nt = 0; nt < 6; ++nt)
#pragma unroll
            for (int q = 0; q < 4; ++q) acc[mt][nt][q] = 0.0f;

    // ---------------- main K loop ----------------
    for (int c = 0; c < NCHUNK; ++c) {
        const int buf = c & 1;
        __syncthreads();   // prior chunk compute done

        // STS A (hi/lo)
        {
            char* ad = base + arow * ASTR + akh * 2;
#pragma unroll
            for (int j = 0; j < 8; ++j) {
                *(uint2*)(ad + OFF_AH + j * 8) = ah[j];
                *(uint2*)(ad + OFF_AL + j * 8) = al[j];
            }
        }
        if (c + 1 < NCHUNK) {
#pragma unroll
            for (int t = 0; t < 6; ++t) {
                int isLo = (t >= 3);
                int r = tid + (t - 3 * isLo) * 256;   // 0..767
                int n = r >> 3, q = r & 7;
                const char* src = (const char*)(isLo ? g_Blo : g_Bhi)
                                  + n * 1024 + (c + 1) * 128 + q * 16;
                cp16(sbase + OFF_B + (buf ^ 1) * BBUF + isLo * BLO + n * ASTR + q * 16, src);
            }
            CP_COMMIT();
            CP_WAIT1();
        } else {
            CP_WAIT0();
        }
        __syncthreads();

        // prefetch A for next chunk
        if (c + 1 < NCHUNK) {
            const float* src = asrc + (c + 1) * KC;
#pragma unroll
            for (int j = 0; j < 8; ++j)
                split4(*(const float4*)(src + j * 4), ah[j], al[j]);
        }

        // compute chunk c: fragments via direct LDS.32
        {
            const char* Bb = base + OFF_B + buf * BBUF;
#pragma unroll
            for (int ks = 0; ks < 4; ++ks) {
                uint32_t Ah[2][4], Al[2][4], Bh[6][2], Bl[6][2];
#pragma unroll
                for (int mt = 0; mt < 2; ++mt) {
                    const char* pa = base + (m0w + mt * 16 + g) * ASTR + ks * 32 + tg4;
                    Ah[mt][0] = *(const uint32_t*)(pa + OFF_AH);
                    Ah[mt][1] = *(const uint32_t*)(pa + OFF_AH + 8 * ASTR);
                    Ah[mt][2] = *(const uint32_t*)(pa + OFF_AH + 16);
                    Ah[mt][3] = *(const uint32_t*)(pa + OFF_AH + 8 * ASTR + 16);
                    Al[mt][0] = *(const uint32_t*)(pa + OFF_AL);
                    Al[mt][1] = *(const uint32_t*)(pa + OFF_AL + 8 * ASTR);
                    Al[mt][2] = *(const uint32_t*)(pa + OFF_AL + 16);
                    Al[mt][3] = *(const uint32_t*)(pa + OFF_AL + 8 * ASTR + 16);
                }
#pragma unroll
                for (int nt = 0; nt < 6; ++nt) {
                    const char* pb = Bb + (n0w + nt * 8 + g) * ASTR + ks * 32 + tg4;
                    Bh[nt][0] = *(const uint32_t*)(pb);
                    Bh[nt][1] = *(const uint32_t*)(pb + 16);
                    Bl[nt][0] = *(const uint32_t*)(pb + BLO);
                    Bl[nt][1] = *(const uint32_t*)(pb + BLO + 16);
                }
#pragma unroll
                for (int mt = 0; mt < 2; ++mt)
#pragma unroll
                    for (int nt = 0; nt < 6; ++nt) {
                        mma16816(acc[mt][nt], Ah[mt], Bh[nt]);
                        mma16816(acc[mt][nt], Ah[mt], Bl[nt]);
                        mma16816(acc[mt][nt], Al[mt], Bh[nt]);
                    }
            }
        }
    }
    __syncthreads();

    // ---------------- D store ----------------
#pragma unroll
    for (int mt = 0; mt < 2; ++mt)
#pragma unroll
        for (int nt = 0; nt < 6; ++nt) {
            int r = m0w + mt * 16 + (l >> 2);
            int cb = n0w + nt * 8 + 2 * (l & 3);
            Dfp[r * DSTR + cb]           = acc[mt][nt][0];
            Dfp[r * DSTR + cb + 1]       = acc[mt][nt][1];
            Dfp[(r + 8) * DSTR + cb]     = acc[mt][nt][2];
            Dfp[(r + 8) * DSTR + cb + 1] = acc[mt][nt][3];
        }
    __syncthreads();

    // ---------------- fiber: bias, STG, write biased back to D ----------------
    {
        int rq = tid >> 3, cq = (tid & 7) * 4;
        float4 bb = *(float4*)((float*)(base + OFF_BFS) + cq);
#pragma unroll
        for (int i = 0; i < 4; ++i) {
            int r = rq + i * 32;
            float4 dv = *(float4*)&Dfp[r * DSTR + cq];
            dv.x += bb.x; dv.y += bb.y; dv.z += bb.z; dv.w += bb.w;
            *(float4*)(fiber_out + (size_t)(mblock + r) * 32 + cq) = dv;
            *(float4*)&Dfp[r * DSTR + cq] = dv;
        }
    }
    __syncthreads();

    // ---------------- pass 2: h += fiber @ Ws2, bias, GELU (fp32 FFMA) ----------------
    {
        const int m  = tid >> 1;
        const int nb = (tid & 1) * 32;
        float fib[32];
#pragma unroll
        for (int q = 0; q < 8; ++q)
            *(float4*)&fib[q * 4] = *(float4*)&Dfp[m * DSTR + q * 4];

        float hacc[32];
#pragma unroll
        for (int q = 0; q < 32; ++q) hacc[q] = 0.0f;

        const float* Wp = (const float*)(base + OFF_WS2);
#pragma unroll
        for (int kf = 0; kf < 32; ++kf) {
            float fv = fib[kf];
#pragma unroll
            for (int q = 0; q < 8; ++q) {
                float4 wv = *(const float4*)&Wp[kf * 64 + nb + q * 4];
                hacc[q * 4 + 0] = fmaf(fv, wv.x, hacc[q * 4 + 0]);
                hacc[q * 4 + 1] = fmaf(fv, wv.y, hacc[q * 4 + 1]);
                hacc[q * 4 + 2] = fmaf(fv, wv.z, hacc[q * 4 + 2]);
                hacc[q * 4 + 3] = fmaf(fv, wv.w, hacc[q * 4 + 3]);
            }
        }
        const float* b1p = (const float*)(base + OFF_B1S);
        const float is2 = 0.70710678118654752f;
#pragma unroll
        for (int q = 0; q < 32; ++q) {
            float x = Dfp[m * DSTR + 32 + nb + q] + hacc[q] + b1p[nb + q];
            Dfp[m * DSTR + 32 + nb + q] = 0.5f * x * (1.0f + erff(x * is2));
        }
    }
    __syncthreads();

    // ---------------- delta: h @ w2 + b2 -> softplus -> clip ----------------
    if (tid < TM) {
        float a2 = b2[0];
        const float* w2p = (const float*)(base + OFF_W2S);
#pragma unroll
        for (int q = 0; q < 16; ++q) {
            float4 h4 = *(float4*)&Dfp[tid * DSTR + 32 + q * 4];
            float4 w4 = *(const float4*)&w2p[q * 4];
            a2 = fmaf(h4.x, w4.x, a2);
            a2 = fmaf(h4.y, w4.y, a2);
            a2 = fmaf(h4.z, w4.z, a2);
            a2 = fmaf(h4.w, w4.w, a2);
        }
        float sp = (a2 > 20.0f) ? a2 : log1pf(expf(a2));
        sp = fminf(fmaxf(sp, 0.0f), 1.0f);
        delta_out[mblock + tid] = sp;
    }
}

// -------- EMA scan (unchanged, known-good) --------
#define C8   0.43046721f
#define C16  0.18530201888518410f
#define C32  0.034336838202925124f
#define C64  0.0011790184577738583f
#define C128 1.3900845237714473e-06f
#define C256 1.9323349832288915e-12f
#define C512 3.7339184874102004e-24f
#define SCAN_T 512

__global__ void cf_scan_kernel(const float* __restrict__ delta,
                               const float* __restrict__ lambda_gate,
                               float* __restrict__ field_out,
                               float* __restrict__ gate_out,
                               int S)
{
    const int b = blockIdx.x;
    const float* d = delta + (size_t)b * S;
    float* f = field_out + (size_t)b * S;
    float* g = gate_out + (size_t)b * S;
    const float lam = *lambda_gate;

    const int tid = threadIdx.x;
    const int lane = tid & 31;
    const int warp = tid >> 5;
    const int base = tid * 8;

    float4 v0 = *(const float4*)(d + base);
    float4 v1 = *(const float4*)(d + base + 4);
    float vals[8] = {v0.x, v0.y, v0.z, v0.w, v1.x, v1.y, v1.z, v1.w};
    float bacc = 0.0f;
#pragma unroll
    for (int i = 0; i < 8; ++i) bacc = fmaf(0.9f, bacc, 0.1f * vals[i]);

    float inc = bacc;
    {
        float p;
        p = __shfl_up_sync(0xffffffffu, inc, 1);  if (lane >= 1)  inc = fmaf(C8,   p, inc);
        p = __shfl_up_sync(0xffffffffu, inc, 2);  if (lane >= 2)  inc = fmaf(C16,  p, inc);
        p = __shfl_up_sync(0xffffffffu, inc, 4);  if (lane >= 4)  inc = fmaf(C32,  p, inc);
        p = __shfl_up_sync(0xffffffffu, inc, 8);  if (lane >= 8)  inc = fmaf(C64,  p, inc);
        p = __shfl_up_sync(0xffffffffu, inc, 16); if (lane >= 16) inc = fmaf(C128, p, inc);
    }
    float lane_excl = __shfl_up_sync(0xffffffffu, inc, 1);
    if (lane == 0) lane_excl = 0.0f;

    __shared__ float ws[16];
    __shared__ float wc[16];
    if (lane == 31) ws[warp] = inc;
    __syncthreads();
    if (tid < 16) {
        float wv = ws[tid];
        float p;
        p = __shfl_up_sync(0x0000ffffu, wv, 1); if (tid >= 1) wv = fmaf(C256, p, wv);
        p = __shfl_up_sync(0x0000ffffu, wv, 2); if (tid >= 2) wv = fmaf(C512, p, wv);
        wc[tid] = wv;
    }
    __syncthreads();

    float dec = 1.0f;
    if (lane & 1)  dec *= C8;
    if (lane & 2)  dec *= C16;
    if (lane & 4)  dec *= C32;
    if (lane & 8)  dec *= C64;
    if (lane & 16) dec *= C128;

    const float wcarry = (warp == 0) ? 0.0f : wc[warp - 1];
    float fld = fmaf(dec, wcarry, lane_excl);

    float fo[8], go[8];
#pragma unroll
    for (int i = 0; i < 8; ++i) {
        fld = fmaf(0.9f, fld, 0.1f * vals[i]);
        float fc = fminf(fmaxf(fld, 0.0f), 10.0f);
        fo[i] = fc;
        go[i] = 1.0f / (1.0f + expf(lam * fc));
    }
    *(float4*)(f + base)     = make_float4(fo[0], fo[1], fo[2], fo[3]);
    *(float4*)(f + base + 4) = make_float4(fo[4], fo[5], fo[6], fo[7]);
    *(float4*)(g + base)     = make_float4(go[0], go[1], go[2], go[3]);
    *(float4*)(g + base + 4) = make_float4(go[4], go[5], go[6], go[7]);
}

extern "C" void kernel_launch(void* const* d_in, const int* in_sizes, int n_in,
                              void* d_out, int out_size)
{
    const float* hidden = (const float*)d_in[0];
    const float* wf     = (const float*)d_in[1];
    const float* bf     = (const float*)d_in[2];
    const float* w1     = (const float*)d_in[3];
    const float* b1     = (const float*)d_in[4];
    const float* w2     = (const float*)d_in[5];
    const float* b2     = (const float*)d_in[6];
    const float* lam    = (const float*)d_in[7];

    const int Ntok = in_sizes[0] / D_MODEL;   // 32768
    float* out   = (float*)d_out;
    float* gate  = out;
    float* field = out + Ntok;
    float* delta = out + 2 * Ntok;
    float* fiber = out + 3 * Ntok;

    cudaFuncSetAttribute(cf_mma_kernel, cudaFuncAttributeMaxDynamicSharedMemorySize, SMEM_BYTES);

    cf_prep_kernel<<<192, 256>>>(wf, w1);
    cf_mma_kernel<<<Ntok / TM, THREADS, SMEM_BYTES>>>(hidden, bf, b1, w1, w2, b2, fiber, delta);
    cf_scan_kernel<<<Ntok / SEQ_S, SCAN_T>>>(delta, lam, field, gate, SEQ_S);
}